// round 2
// baseline (speedup 1.0000x reference)
#include <cuda_runtime.h>

// ---------------- repacked weights (consumption order, float4-friendly) ----------------
// layout (floats):
//   [0    ..192 )  w12p[(ci*3+k)*8  + co]
//   [192  ..576 )  w21p[(ci*3+k)*16 + co]
//   [576  ..1344)  w22p[(ci*3+k)*16 + co]
//   [1344 ..3648)  Wlp [(t*16+ch)*24 + o]
//   [3648 ..3672)  w11p[k*8 + co]
//   [3672 ..3680)  b11
//   [3680 ..3688)  b12
//   [3688 ..3704)  b21
//   [3704 ..3720)  b22
//   [3720 ..3744)  bl
#define PACK_FLOATS 3744
__device__ __align__(16) float g_pack[PACK_FLOATS];

__global__ void repack_kernel(
    const float* __restrict__ w11, const float* __restrict__ b11,
    const float* __restrict__ w12, const float* __restrict__ b12,
    const float* __restrict__ w21, const float* __restrict__ b21,
    const float* __restrict__ w22, const float* __restrict__ b22,
    const float* __restrict__ Wl,  const float* __restrict__ bl)
{
    int tid = threadIdx.x;
    for (int i = tid; i < 192;  i += 256) g_pack[i]        = w12[(i & 7)  * 24 + (i >> 3)];
    for (int i = tid; i < 384;  i += 256) g_pack[192 + i]  = w21[(i & 15) * 24 + (i >> 4)];
    for (int i = tid; i < 768;  i += 256) g_pack[576 + i]  = w22[(i & 15) * 48 + (i >> 4)];
    for (int i = tid; i < 2304; i += 256) {
        int o = i % 24; int r = i / 24;          // r = t*16 + ch
        g_pack[1344 + i] = Wl[o * 96 + (r & 15) * 6 + (r >> 4)];
    }
    if (tid < 24) g_pack[3648 + tid] = w11[(tid & 7) * 3 + (tid >> 3)];
    if (tid < 8)  g_pack[3672 + tid] = b11[tid];
    if (tid < 8)  g_pack[3680 + tid] = b12[tid];
    if (tid < 16) g_pack[3688 + tid] = b21[tid];
    if (tid < 16) g_pack[3704 + tid] = b22[tid];
    if (tid < 24) g_pack[3720 + tid] = bl[tid];
}

#define FMA8(A, W0, W1, V) do { \
    A[0]=fmaf((W0).x,(V),A[0]); A[1]=fmaf((W0).y,(V),A[1]); \
    A[2]=fmaf((W0).z,(V),A[2]); A[3]=fmaf((W0).w,(V),A[3]); \
    A[4]=fmaf((W1).x,(V),A[4]); A[5]=fmaf((W1).y,(V),A[5]); \
    A[6]=fmaf((W1).z,(V),A[6]); A[7]=fmaf((W1).w,(V),A[7]); } while(0)

#define FMA16(A, W0, W1, W2, W3, V) do { \
    A[0] =fmaf((W0).x,(V),A[0] ); A[1] =fmaf((W0).y,(V),A[1] ); \
    A[2] =fmaf((W0).z,(V),A[2] ); A[3] =fmaf((W0).w,(V),A[3] ); \
    A[4] =fmaf((W1).x,(V),A[4] ); A[5] =fmaf((W1).y,(V),A[5] ); \
    A[6] =fmaf((W1).z,(V),A[6] ); A[7] =fmaf((W1).w,(V),A[7] ); \
    A[8] =fmaf((W2).x,(V),A[8] ); A[9] =fmaf((W2).y,(V),A[9] ); \
    A[10]=fmaf((W2).z,(V),A[10]); A[11]=fmaf((W2).w,(V),A[11]); \
    A[12]=fmaf((W3).x,(V),A[12]); A[13]=fmaf((W3).y,(V),A[13]); \
    A[14]=fmaf((W3).z,(V),A[14]); A[15]=fmaf((W3).w,(V),A[15]); } while(0)

// dynamic smem: 3744 weight floats + p1 buffer [12*8][128 threads]
#define P1_FLOATS (12 * 8 * 128)
#define SMEM_BYTES ((PACK_FLOATS + P1_FLOATS) * 4)

__global__ void __launch_bounds__(128, 3)
cnn_kernel(const float* __restrict__ x, float* __restrict__ out, int n)
{
    extern __shared__ float sm[];
    int tid = threadIdx.x;
    {
        float4*       dst4 = reinterpret_cast<float4*>(sm);
        const float4* src4 = reinterpret_cast<const float4*>(g_pack);
#pragma unroll
        for (int i = 0; i < 8; i++) {
            int idx = tid + i * 128;
            if (idx < PACK_FLOATS / 4) dst4[idx] = src4[idx];
        }
    }
    __syncthreads();

    const float* sw12 = sm;
    const float* sw21 = sm + 192;
    const float* sw22 = sm + 576;
    const float* sWl  = sm + 1344;
    const float* sw11 = sm + 3648;
    const float* sb11 = sm + 3672;
    const float* sb12 = sm + 3680;
    const float* sb21 = sm + 3688;
    const float* sb22 = sm + 3704;
    const float* sbl  = sm + 3720;
    float* p1t = sm + PACK_FLOATS + tid;   // p1t[(col*8+ch)*128]

    int s = blockIdx.x * 128 + tid;
    if (s >= n) return;

    // ---- input sample ----
    float xv[24];
    {
        const float4* xg = reinterpret_cast<const float4*>(x + (size_t)s * 24);
#pragma unroll
        for (int i = 0; i < 6; i++) {
            float4 v = xg[i];
            xv[4*i] = v.x; xv[4*i+1] = v.y; xv[4*i+2] = v.z; xv[4*i+3] = v.w;
        }
    }

    // ================= stage A: conv11 -> relu -> conv12 -> relu -> pool ==========
    float h1buf[4][8];

    auto computeH1 = [&](int pos) {
        float xm = (pos > 0)  ? xv[pos - 1] : 0.f;
        float xc = xv[pos];
        float xp = (pos < 23) ? xv[pos + 1] : 0.f;
        float* d = h1buf[pos & 3];
#pragma unroll
        for (int c = 0; c < 8; c++)
            d[c] = fmaxf(fmaf(sw11[16 + c], xp,
                        fmaf(sw11[8 + c], xc,
                        fmaf(sw11[c], xm, sb11[c]))), 0.f);
    };

    computeH1(0); computeH1(1); computeH1(2);

#pragma unroll
    for (int t = 0; t < 12; t++) {
        float a0[8], a1[8];
#pragma unroll
        for (int c = 0; c < 8; c++) { float b = sb12[c]; a0[c] = b; a1[c] = b; }
#pragma unroll
        for (int ci = 0; ci < 8; ci++) {
            float hm = (t == 0)  ? 0.f : h1buf[(2*t + 3) & 3][ci];  // pos 2t-1
            float h0 = h1buf[(2*t) & 3][ci];
            float hA = h1buf[(2*t + 1) & 3][ci];
            float hp = (t == 11) ? 0.f : h1buf[(2*t + 2) & 3][ci];
            float in0[3] = {hm, h0, hA};
            float in1[3] = {h0, hA, hp};
#pragma unroll
            for (int k = 0; k < 3; k++) {
                const float* wb = sw12 + (ci * 3 + k) * 8;
                float4 w0 = *(const float4*)(wb);
                float4 w1 = *(const float4*)(wb + 4);
                FMA8(a0, w0, w1, in0[k]);
                FMA8(a1, w0, w1, in1[k]);
            }
        }
#pragma unroll
        for (int c = 0; c < 8; c++)
            p1t[(t * 8 + c) * 128] = fmaxf(fmaxf(a0[c], a1[c]), 0.f);
        if (t < 11) computeH1(2*t + 3);
        if (t < 10) computeH1(2*t + 4);
    }

    // ================= stage B: conv21 -> relu -> conv22 -> relu -> pool -> linear =====
    float h3buf[4][16];

    // computes h3(posA) and optionally h3(posA+1) sharing weight loads
    auto computeH3pair = [&](int posA, bool doB, bool zeroB) {
        float dA[16], dB[16];
#pragma unroll
        for (int c = 0; c < 16; c++) { float b = sb21[c]; dA[c] = b; dB[c] = b; }
#pragma unroll
        for (int ci = 0; ci < 8; ci++) {
#pragma unroll
            for (int k = 0; k < 3; k++) {
                const float* wb = sw21 + (ci * 3 + k) * 16;
                float4 w0 = *(const float4*)(wb);
                float4 w1 = *(const float4*)(wb + 4);
                float4 w2 = *(const float4*)(wb + 8);
                float4 w3 = *(const float4*)(wb + 12);
                int colA = posA + k - 1;
                if (colA >= 0 && colA < 12) {
                    float pv = p1t[(colA * 8 + ci) * 128];
                    FMA16(dA, w0, w1, w2, w3, pv);
                }
                if (doB) {
                    int colB = posA + k;
                    if (colB < 12) {
                        float pv = p1t[(colB * 8 + ci) * 128];
                        FMA16(dB, w0, w1, w2, w3, pv);
                    }
                }
            }
        }
        float* oA = h3buf[posA & 3];
#pragma unroll
        for (int c = 0; c < 16; c++) oA[c] = fmaxf(dA[c], 0.f);
        if (doB) {
            float* oB = h3buf[(posA + 1) & 3];
#pragma unroll
            for (int c = 0; c < 16; c++) oB[c] = fmaxf(dB[c], 0.f);
        }
        if (zeroB) {
            float* oB = h3buf[(posA + 1) & 3];
#pragma unroll
            for (int c = 0; c < 16; c++) oB[c] = 0.f;
        }
    };

    float acc[24];
#pragma unroll
    for (int i = 0; i < 6; i++) {
        float4 b = *(const float4*)(sbl + 4 * i);
        acc[4*i] = b.x; acc[4*i+1] = b.y; acc[4*i+2] = b.z; acc[4*i+3] = b.w;
    }

    computeH3pair(0, true,  false);   // h3(0), h3(1)
    computeH3pair(2, false, false);   // h3(2)

#pragma unroll
    for (int t2 = 0; t2 < 6; t2++) {
        float a0[16], a1[16];
#pragma unroll
        for (int c = 0; c < 16; c++) { float b = sb22[c]; a0[c] = b; a1[c] = b; }
#pragma unroll
        for (int ci = 0; ci < 16; ci++) {
            float gm = (t2 == 0) ? 0.f : h3buf[(2*t2 + 3) & 3][ci];  // pos 2t2-1
            float g0 = h3buf[(2*t2) & 3][ci];
            float g1 = h3buf[(2*t2 + 1) & 3][ci];
            float g2 = h3buf[(2*t2 + 2) & 3][ci];                    // t2=5: zeros (pos 12)
            float in0[3] = {gm, g0, g1};
            float in1[3] = {g0, g1, g2};
#pragma unroll
            for (int k = 0; k < 3; k++) {
                const float* wb = sw22 + (ci * 3 + k) * 16;
                float4 w0 = *(const float4*)(wb);
                float4 w1 = *(const float4*)(wb + 4);
                float4 w2 = *(const float4*)(wb + 8);
                float4 w3 = *(const float4*)(wb + 12);
                FMA16(a0, w0, w1, w2, w3, in0[k]);
                FMA16(a1, w0, w1, w2, w3, in1[k]);
            }
        }
        // pool + fused linear
#pragma unroll
        for (int ch = 0; ch < 16; ch++) {
            float v = fmaxf(fmaxf(a0[ch], a1[ch]), 0.f);
            const float* wl = sWl + (t2 * 16 + ch) * 24;
#pragma unroll
            for (int i = 0; i < 6; i++) {
                float4 w = *(const float4*)(wl + 4 * i);
                acc[4*i]   = fmaf(w.x, v, acc[4*i]);
                acc[4*i+1] = fmaf(w.y, v, acc[4*i+1]);
                acc[4*i+2] = fmaf(w.z, v, acc[4*i+2]);
                acc[4*i+3] = fmaf(w.w, v, acc[4*i+3]);
            }
        }
        if (t2 < 5)
            computeH3pair(2*t2 + 3, /*doB=*/(2*t2 + 4 <= 11), /*zeroB=*/(2*t2 + 4 == 12));
    }

    // ---- store output sample ----
    {
        float4* og = reinterpret_cast<float4*>(out + (size_t)s * 24);
#pragma unroll
        for (int i = 0; i < 6; i++)
            og[i] = make_float4(acc[4*i], acc[4*i+1], acc[4*i+2], acc[4*i+3]);
    }
}

extern "C" void kernel_launch(void* const* d_in, const int* in_sizes, int n_in,
                              void* d_out, int out_size)
{
    const float* x = (const float*)d_in[0];

    repack_kernel<<<1, 256>>>(
        (const float*)d_in[1], (const float*)d_in[2],
        (const float*)d_in[3], (const float*)d_in[4],
        (const float*)d_in[5], (const float*)d_in[6],
        (const float*)d_in[7], (const float*)d_in[8],
        (const float*)d_in[9], (const float*)d_in[10]);

    static bool attr_set = false;
    if (!attr_set) {
        cudaFuncSetAttribute(cnn_kernel,
                             cudaFuncAttributeMaxDynamicSharedMemorySize, SMEM_BYTES);
        attr_set = true;
    }

    int nSamples = in_sizes[0] / 24;   // 512*256 = 131072
    int blocks = (nSamples + 127) / 128;
    cnn_kernel<<<blocks, 128, SMEM_BYTES>>>(x, (float*)d_out, nSamples);
}

// round 3
// speedup vs baseline: 4.6797x; 4.6797x over previous
#include <cuda_runtime.h>

// ---------------- packed weights, repacked into consumption order ----------------
// layout (floats) in g_pack / c_pack:
//   [0    ..192 )  w12p[(ci*3+k)*8  + co]       (co contiguous -> {co,co+1} pairs)
//   [192  ..576 )  w21p[(ci*3+k)*16 + co]
//   [576  ..1344)  w22p[(ci*3+k)*16 + co]
//   [1344 ..3648)  Wlp [(t2*16+ch)*24 + o]      (o contiguous -> {o,o+1} pairs)
//   [3648 ..3672)  w11p[k*8 + co]
//   [3672 ..3680)  b11
//   [3680 ..3688)  b12
//   [3688 ..3704)  b21
//   [3704 ..3720)  b22
//   [3720 ..3744)  bl
#define PACKN 3744
__device__ __align__(16) float g_pack[PACKN];
__constant__ __align__(16) float c_pack[PACKN];

__global__ void repack_kernel(
    const float* __restrict__ w11, const float* __restrict__ b11,
    const float* __restrict__ w12, const float* __restrict__ b12,
    const float* __restrict__ w21, const float* __restrict__ b21,
    const float* __restrict__ w22, const float* __restrict__ b22,
    const float* __restrict__ Wl,  const float* __restrict__ bl)
{
    int tid = threadIdx.x;
    for (int i = tid; i < 192;  i += 256) g_pack[i]       = w12[(i & 7)  * 24 + (i >> 3)];
    for (int i = tid; i < 384;  i += 256) g_pack[192 + i] = w21[(i & 15) * 24 + (i >> 4)];
    for (int i = tid; i < 768;  i += 256) g_pack[576 + i] = w22[(i & 15) * 48 + (i >> 4)];
    for (int i = tid; i < 2304; i += 256) {
        int o = i % 24; int r = i / 24;          // r = t2*16 + ch, feature = ch*6 + t2
        g_pack[1344 + i] = Wl[o * 96 + (r & 15) * 6 + (r >> 4)];
    }
    if (tid < 24) g_pack[3648 + tid] = w11[(tid & 7) * 3 + (tid >> 3)];
    if (tid < 8)  g_pack[3672 + tid] = b11[tid];
    if (tid < 8)  g_pack[3680 + tid] = b12[tid];
    if (tid < 16) g_pack[3688 + tid] = b21[tid];
    if (tid < 16) g_pack[3704 + tid] = b22[tid];
    if (tid < 24) g_pack[3720 + tid] = bl[tid];
}

// ---------------- packed f32x2 helpers ----------------
typedef unsigned long long u64;

__device__ __forceinline__ u64 pk2(float lo, float hi) {
    u64 r; asm("mov.b64 %0,{%1,%2};" : "=l"(r) : "f"(lo), "f"(hi)); return r;
}
__device__ __forceinline__ float2 upk2(u64 v) {
    float2 f; asm("mov.b64 {%0,%1},%2;" : "=f"(f.x), "=f"(f.y) : "l"(v)); return f;
}
__device__ __forceinline__ u64 ffma2(u64 a, u64 b, u64 c) {
    u64 d; asm("fma.rn.f32x2 %0,%1,%2,%3;" : "=l"(d) : "l"(a), "l"(b), "l"(c)); return d;
}
// 64-bit constant load (pair of adjacent floats), idx must be even
__device__ __forceinline__ u64 cpk(int idx) {
    return *reinterpret_cast<const u64*>(&c_pack[idx]);
}

__global__ void __launch_bounds__(128)
cnn_kernel(const float* __restrict__ x, float* __restrict__ out, int n)
{
    int s = blockIdx.x * 128 + threadIdx.x;
    if (s >= n) return;

    // ---- input sample (24 floats) ----
    float xv[24];
    {
        const float4* xg = reinterpret_cast<const float4*>(x + (size_t)s * 24);
#pragma unroll
        for (int i = 0; i < 6; i++) {
            float4 v = xg[i];
            xv[4*i] = v.x; xv[4*i+1] = v.y; xv[4*i+2] = v.z; xv[4*i+3] = v.w;
        }
    }

    // ================= stage A: conv11 -> relu -> conv12 -> relu -> pool ==========
    float h1[4][8];
    auto H1 = [&](int pos) {
        float xm = (pos > 0)  ? xv[pos - 1] : 0.f;
        float xc = xv[pos];
        float xp = (pos < 23) ? xv[pos + 1] : 0.f;
        float* d = h1[pos & 3];
#pragma unroll
        for (int c = 0; c < 8; c++)
            d[c] = fmaxf(fmaf(c_pack[3648 + 16 + c], xp,
                         fmaf(c_pack[3648 + 8 + c],  xc,
                         fmaf(c_pack[3648 + c],      xm, c_pack[3672 + c]))), 0.f);
    };
    H1(0); H1(1); H1(2);

    float p1[8][12];
#pragma unroll
    for (int t = 0; t < 12; t++) {
        u64 Ae[4], Ao[4];                       // co-pair accumulators, pos even/odd
#pragma unroll
        for (int p = 0; p < 4; p++) { u64 b = cpk(3680 + 2*p); Ae[p] = b; Ao[p] = b; }
#pragma unroll
        for (int ci = 0; ci < 8; ci++) {
#pragma unroll
            for (int k = 0; k < 3; k++) {
                int pe = 2*t + k - 1, po = 2*t + k;
                float ge = (pe < 0) ? 0.f : h1[pe & 3][ci];
                float go = (po > 23) ? 0.f : h1[po & 3][ci];
                u64 se = pk2(ge, ge), so = pk2(go, go);
#pragma unroll
                for (int p = 0; p < 4; p++) {
                    u64 w = cpk((ci*3 + k) * 8 + 2*p);
                    Ae[p] = ffma2(w, se, Ae[p]);
                    Ao[p] = ffma2(w, so, Ao[p]);
                }
            }
        }
        // relu + pool (max over pos pair, then vs 0)
#pragma unroll
        for (int p = 0; p < 4; p++) {
            float2 e = upk2(Ae[p]), o = upk2(Ao[p]);
            p1[2*p][t]     = fmaxf(fmaxf(e.x, o.x), 0.f);
            p1[2*p + 1][t] = fmaxf(fmaxf(e.y, o.y), 0.f);
        }
        if (t < 11) H1(2*t + 3);
        if (t < 10) H1(2*t + 4);
    }

    // ================= stage B: conv21 -> relu -> conv22 -> relu -> pool -> linear =====
    float h3[4][16];
    auto H3pair = [&](int posA, bool doB, bool zeroB) {
        u64 DA[8], DB[8];
#pragma unroll
        for (int p = 0; p < 8; p++) { u64 b = cpk(3688 + 2*p); DA[p] = b; DB[p] = b; }
#pragma unroll
        for (int ci = 0; ci < 8; ci++) {
#pragma unroll
            for (int k = 0; k < 3; k++) {
                int cA = posA + k - 1, cB = posA + k;
                float gA = (cA < 0 || cA > 11) ? 0.f : p1[ci][cA];
                float gB = (cB > 11) ? 0.f : p1[ci][cB];
                u64 sA = pk2(gA, gA), sB = pk2(gB, gB);
#pragma unroll
                for (int p = 0; p < 8; p++) {
                    u64 w = cpk(192 + (ci*3 + k) * 16 + 2*p);
                    DA[p] = ffma2(w, sA, DA[p]);
                    if (doB) DB[p] = ffma2(w, sB, DB[p]);
                }
            }
        }
        float* oA = h3[posA & 3];
#pragma unroll
        for (int p = 0; p < 8; p++) {
            float2 v = upk2(DA[p]);
            oA[2*p] = fmaxf(v.x, 0.f); oA[2*p + 1] = fmaxf(v.y, 0.f);
        }
        if (doB) {
            float* oB = h3[(posA + 1) & 3];
#pragma unroll
            for (int p = 0; p < 8; p++) {
                float2 v = upk2(DB[p]);
                oB[2*p] = fmaxf(v.x, 0.f); oB[2*p + 1] = fmaxf(v.y, 0.f);
            }
        }
        if (zeroB) {
            float* oB = h3[(posA + 1) & 3];
#pragma unroll
            for (int c = 0; c < 16; c++) oB[c] = 0.f;
        }
    };

    u64 acc2[12];                               // output-pair linear accumulators
#pragma unroll
    for (int q = 0; q < 12; q++) acc2[q] = cpk(3720 + 2*q);

    H3pair(0, true,  false);                    // h3(0), h3(1)
    H3pair(2, false, false);                    // h3(2)

#pragma unroll
    for (int t2 = 0; t2 < 6; t2++) {
        u64 Ae[8], Ao[8];                       // co-pair accumulators for pos 2t2, 2t2+1
#pragma unroll
        for (int p = 0; p < 8; p++) { u64 b = cpk(3704 + 2*p); Ae[p] = b; Ao[p] = b; }
#pragma unroll
        for (int ci = 0; ci < 16; ci++) {
#pragma unroll
            for (int k = 0; k < 3; k++) {
                int pe = 2*t2 + k - 1, po = 2*t2 + k;
                float ge = (pe < 0) ? 0.f : h3[pe & 3][ci];
                float go = h3[po & 3][ci];      // pos 12 slot holds zeros (zeroB)
                u64 se = pk2(ge, ge), so = pk2(go, go);
#pragma unroll
                for (int p = 0; p < 8; p++) {
                    u64 w = cpk(576 + (ci*3 + k) * 16 + 2*p);
                    Ae[p] = ffma2(w, se, Ae[p]);
                    Ao[p] = ffma2(w, so, Ao[p]);
                }
            }
        }
        // relu + pool + fused linear (output-pair packed)
#pragma unroll
        for (int p = 0; p < 8; p++) {
            float2 e = upk2(Ae[p]), o = upk2(Ao[p]);
            float v0 = fmaxf(fmaxf(e.x, o.x), 0.f);     // ch = 2p
            float v1 = fmaxf(fmaxf(e.y, o.y), 0.f);     // ch = 2p+1
            u64 s0 = pk2(v0, v0), s1 = pk2(v1, v1);
            int r0 = 1344 + (t2*16 + 2*p) * 24;
            int r1 = r0 + 24;
#pragma unroll
            for (int q = 0; q < 12; q++) {
                acc2[q] = ffma2(cpk(r0 + 2*q), s0, acc2[q]);
                acc2[q] = ffma2(cpk(r1 + 2*q), s1, acc2[q]);
            }
        }
        if (t2 < 5)
            H3pair(2*t2 + 3, (2*t2 + 4 <= 11), (2*t2 + 4 == 12));
    }

    // ---- store output sample (24 floats) ----
    {
        float res[24];
#pragma unroll
        for (int q = 0; q < 12; q++) {
            float2 v = upk2(acc2[q]);
            res[2*q] = v.x; res[2*q + 1] = v.y;
        }
        float4* og = reinterpret_cast<float4*>(out + (size_t)s * 24);
#pragma unroll
        for (int i = 0; i < 6; i++)
            og[i] = make_float4(res[4*i], res[4*i+1], res[4*i+2], res[4*i+3]);
    }
}

extern "C" void kernel_launch(void* const* d_in, const int* in_sizes, int n_in,
                              void* d_out, int out_size)
{
    const float* x = (const float*)d_in[0];

    repack_kernel<<<1, 256>>>(
        (const float*)d_in[1], (const float*)d_in[2],
        (const float*)d_in[3], (const float*)d_in[4],
        (const float*)d_in[5], (const float*)d_in[6],
        (const float*)d_in[7], (const float*)d_in[8],
        (const float*)d_in[9], (const float*)d_in[10]);

    // copy repacked weights into constant bank (D2D, graph-capturable)
    void* c_addr = nullptr;
    void* g_addr = nullptr;
    cudaGetSymbolAddress(&c_addr, c_pack);
    cudaGetSymbolAddress(&g_addr, g_pack);
    cudaMemcpyAsync(c_addr, g_addr, PACKN * sizeof(float), cudaMemcpyDeviceToDevice, 0);

    int nSamples = in_sizes[0] / 24;   // 512*256 = 131072
    int blocks = (nSamples + 127) / 128;
    cnn_kernel<<<blocks, 128>>>(x, (float*)d_out, nSamples);
}

// round 4
// speedup vs baseline: 6.4749x; 1.3836x over previous
#include <cuda_runtime.h>

// ---------------- packed weights, repacked into consumption order ----------------
//   [0    ..192 )  w12p[(ci*3+k)*8  + co]
//   [192  ..576 )  w21p[(ci*3+k)*16 + co]
//   [576  ..1344)  w22p[(ci*3+k)*16 + co]
//   [1344 ..3648)  Wlp [(t2*16+ch)*24 + o]
//   [3648 ..3672)  w11p[k*8 + co]
//   [3672 ..3680)  b11   [3680..3688) b12   [3688..3704) b21
//   [3704 ..3720)  b22   [3720..3744) bl
#define PACKN 3744
__device__ __align__(16) float g_pack[PACKN];
__constant__ __align__(16) float c_pack[PACKN];

__global__ void repack_kernel(
    const float* __restrict__ w11, const float* __restrict__ b11,
    const float* __restrict__ w12, const float* __restrict__ b12,
    const float* __restrict__ w21, const float* __restrict__ b21,
    const float* __restrict__ w22, const float* __restrict__ b22,
    const float* __restrict__ Wl,  const float* __restrict__ bl)
{
    int tid = threadIdx.x;
    for (int i = tid; i < 192;  i += 256) g_pack[i]       = w12[(i & 7)  * 24 + (i >> 3)];
    for (int i = tid; i < 384;  i += 256) g_pack[192 + i] = w21[(i & 15) * 24 + (i >> 4)];
    for (int i = tid; i < 768;  i += 256) g_pack[576 + i] = w22[(i & 15) * 48 + (i >> 4)];
    for (int i = tid; i < 2304; i += 256) {
        int o = i % 24; int r = i / 24;          // r = t2*16 + ch, feature = ch*6 + t2
        g_pack[1344 + i] = Wl[o * 96 + (r & 15) * 6 + (r >> 4)];
    }
    if (tid < 24) g_pack[3648 + tid] = w11[(tid & 7) * 3 + (tid >> 3)];
    if (tid < 8)  g_pack[3672 + tid] = b11[tid];
    if (tid < 8)  g_pack[3680 + tid] = b12[tid];
    if (tid < 16) g_pack[3688 + tid] = b21[tid];
    if (tid < 16) g_pack[3704 + tid] = b22[tid];
    if (tid < 24) g_pack[3720 + tid] = bl[tid];
}

// ---------------- packed f32x2 helpers ----------------
typedef unsigned long long u64;

__device__ __forceinline__ u64 pk2(float lo, float hi) {
    u64 r; asm("mov.b64 %0,{%1,%2};" : "=l"(r) : "f"(lo), "f"(hi)); return r;
}
__device__ __forceinline__ float2 upk2(u64 v) {
    float2 f; asm("mov.b64 {%0,%1},%2;" : "=f"(f.x), "=f"(f.y) : "l"(v)); return f;
}
__device__ __forceinline__ u64 ffma2(u64 a, u64 b, u64 c) {
    u64 d; asm("fma.rn.f32x2 %0,%1,%2,%3;" : "=l"(d) : "l"(a), "l"(b), "l"(c)); return d;
}
__device__ __forceinline__ u64 cpk(int idx) {           // 64-bit constant load, idx even
    return *reinterpret_cast<const u64*>(&c_pack[idx]);
}

// per-thread p1 scratch in dynamic smem: p1[(ci*12+col)*128 + tid]
#define P1_STRIDE 128
#define SMEM_BYTES (96 * 128 * 4)

__global__ void __launch_bounds__(128, 3)
cnn_kernel(const float* __restrict__ x, float* __restrict__ out, int n)
{
    extern __shared__ float p1s_base[];
    float* p1s = p1s_base + threadIdx.x;

    int s = blockIdx.x * 128 + threadIdx.x;
    if (s >= n) return;

    // ---- input sample (24 floats) ----
    float xv[24];
    {
        const float4* xg = reinterpret_cast<const float4*>(x + (size_t)s * 24);
#pragma unroll
        for (int i = 0; i < 6; i++) {
            float4 v = xg[i];
            xv[4*i] = v.x; xv[4*i+1] = v.y; xv[4*i+2] = v.z; xv[4*i+3] = v.w;
        }
    }

    // ================= stage A: conv11 -> relu -> conv12 -> relu -> pool ==========
    u64 h1[4][8];                               // pre-splatted (v,v) ring
    auto H1 = [&](int pos) {
        float xm = (pos > 0)  ? xv[pos - 1] : 0.f;
        float xc = xv[pos];
        float xp = (pos < 23) ? xv[pos + 1] : 0.f;
        u64* d = h1[pos & 3];
#pragma unroll
        for (int c = 0; c < 8; c++) {
            float v = fmaxf(fmaf(c_pack[3648 + 16 + c], xp,
                           fmaf(c_pack[3648 + 8 + c],  xc,
                           fmaf(c_pack[3648 + c],      xm, c_pack[3672 + c]))), 0.f);
            d[c] = pk2(v, v);
        }
    };
    H1(0); H1(1); H1(2);

#pragma unroll
    for (int t = 0; t < 12; t++) {
        u64 Ae[4], Ao[4];
#pragma unroll
        for (int p = 0; p < 4; p++) { u64 b = cpk(3680 + 2*p); Ae[p] = b; Ao[p] = b; }
#pragma unroll
        for (int ci = 0; ci < 8; ci++) {
#pragma unroll
            for (int k = 0; k < 3; k++) {
                int pe = 2*t + k - 1, po = 2*t + k;
                u64 se = (pe < 0)  ? 0ull : h1[pe & 3][ci];
                u64 so = (po > 23) ? 0ull : h1[po & 3][ci];
#pragma unroll
                for (int p = 0; p < 4; p++) {
                    u64 w = cpk((ci*3 + k) * 8 + 2*p);
                    Ae[p] = ffma2(w, se, Ae[p]);
                    Ao[p] = ffma2(w, so, Ao[p]);
                }
            }
        }
#pragma unroll
        for (int p = 0; p < 4; p++) {
            float2 e = upk2(Ae[p]), o = upk2(Ao[p]);
            p1s[((2*p)     * 12 + t) * P1_STRIDE] = fmaxf(fmaxf(e.x, o.x), 0.f);
            p1s[((2*p + 1) * 12 + t) * P1_STRIDE] = fmaxf(fmaxf(e.y, o.y), 0.f);
        }
        if (t < 11) H1(2*t + 3);
        if (t < 10) H1(2*t + 4);
    }

    // ================= stage B: conv21 -> relu -> conv22 -> relu -> pool -> linear =====
    float h3[4][16];
    auto H3pair = [&](int posA, bool doB, bool zeroB) {
        u64 DA[8], DB[8];
#pragma unroll
        for (int p = 0; p < 8; p++) { u64 b = cpk(3688 + 2*p); DA[p] = b; DB[p] = b; }
#pragma unroll
        for (int ci = 0; ci < 8; ci++) {
#pragma unroll
            for (int k = 0; k < 3; k++) {
                int cA = posA + k - 1, cB = posA + k;
                float gA = (cA < 0 || cA > 11) ? 0.f : p1s[(ci * 12 + cA) * P1_STRIDE];
                float gB = (cB > 11) ? 0.f : p1s[(ci * 12 + cB) * P1_STRIDE];
                u64 sA = pk2(gA, gA), sB = pk2(gB, gB);
#pragma unroll
                for (int p = 0; p < 8; p++) {
                    u64 w = cpk(192 + (ci*3 + k) * 16 + 2*p);
                    DA[p] = ffma2(w, sA, DA[p]);
                    if (doB) DB[p] = ffma2(w, sB, DB[p]);
                }
            }
        }
        float* oA = h3[posA & 3];
#pragma unroll
        for (int p = 0; p < 8; p++) {
            float2 v = upk2(DA[p]);
            oA[2*p] = fmaxf(v.x, 0.f); oA[2*p + 1] = fmaxf(v.y, 0.f);
        }
        if (doB) {
            float* oB = h3[(posA + 1) & 3];
#pragma unroll
            for (int p = 0; p < 8; p++) {
                float2 v = upk2(DB[p]);
                oB[2*p] = fmaxf(v.x, 0.f); oB[2*p + 1] = fmaxf(v.y, 0.f);
            }
        }
        if (zeroB) {
            float* oB = h3[(posA + 1) & 3];
#pragma unroll
            for (int c = 0; c < 16; c++) oB[c] = 0.f;
        }
    };

    u64 acc2[12];
#pragma unroll
    for (int q = 0; q < 12; q++) acc2[q] = cpk(3720 + 2*q);

    H3pair(0, true,  false);
    H3pair(2, false, false);

#pragma unroll
    for (int t2 = 0; t2 < 6; t2++) {
        u64 Ae[8], Ao[8];
#pragma unroll
        for (int p = 0; p < 8; p++) { u64 b = cpk(3704 + 2*p); Ae[p] = b; Ao[p] = b; }
#pragma unroll
        for (int ci = 0; ci < 16; ci++) {
#pragma unroll
            for (int k = 0; k < 3; k++) {
                int pe = 2*t2 + k - 1, po = 2*t2 + k;
                float ge = (pe < 0) ? 0.f : h3[pe & 3][ci];
                float go = h3[po & 3][ci];      // pos-12 slot pre-zeroed
                u64 se = pk2(ge, ge), so = pk2(go, go);
#pragma unroll
                for (int p = 0; p < 8; p++) {
                    u64 w = cpk(576 + (ci*3 + k) * 16 + 2*p);
                    Ae[p] = ffma2(w, se, Ae[p]);
                    Ao[p] = ffma2(w, so, Ao[p]);
                }
            }
        }
#pragma unroll
        for (int p = 0; p < 8; p++) {
            float2 e = upk2(Ae[p]), o = upk2(Ao[p]);
            float v0 = fmaxf(fmaxf(e.x, o.x), 0.f);
            float v1 = fmaxf(fmaxf(e.y, o.y), 0.f);
            u64 s0 = pk2(v0, v0), s1 = pk2(v1, v1);
            int r0 = 1344 + (t2*16 + 2*p) * 24;
            int r1 = r0 + 24;
#pragma unroll
            for (int q = 0; q < 12; q++) {
                acc2[q] = ffma2(cpk(r0 + 2*q), s0, acc2[q]);
                acc2[q] = ffma2(cpk(r1 + 2*q), s1, acc2[q]);
            }
        }
        if (t2 < 5)
            H3pair(2*t2 + 3, (2*t2 + 4 <= 11), (2*t2 + 4 == 12));
    }

    // ---- store output sample (24 floats) ----
    {
        float res[24];
#pragma unroll
        for (int q = 0; q < 12; q++) {
            float2 v = upk2(acc2[q]);
            res[2*q] = v.x; res[2*q + 1] = v.y;
        }
        float4* og = reinterpret_cast<float4*>(out + (size_t)s * 24);
#pragma unroll
        for (int i = 0; i < 6; i++)
            og[i] = make_float4(res[4*i], res[4*i+1], res[4*i+2], res[4*i+3]);
    }
}

extern "C" void kernel_launch(void* const* d_in, const int* in_sizes, int n_in,
                              void* d_out, int out_size)
{
    const float* x = (const float*)d_in[0];

    repack_kernel<<<1, 256>>>(
        (const float*)d_in[1], (const float*)d_in[2],
        (const float*)d_in[3], (const float*)d_in[4],
        (const float*)d_in[5], (const float*)d_in[6],
        (const float*)d_in[7], (const float*)d_in[8],
        (const float*)d_in[9], (const float*)d_in[10]);

    void* c_addr = nullptr;
    void* g_addr = nullptr;
    cudaGetSymbolAddress(&c_addr, c_pack);
    cudaGetSymbolAddress(&g_addr, g_pack);
    cudaMemcpyAsync(c_addr, g_addr, PACKN * sizeof(float), cudaMemcpyDeviceToDevice, 0);

    static bool attr_set = false;
    if (!attr_set) {
        cudaFuncSetAttribute(cnn_kernel,
                             cudaFuncAttributeMaxDynamicSharedMemorySize, SMEM_BYTES);
        attr_set = true;
    }

    int nSamples = in_sizes[0] / 24;   // 512*256 = 131072
    int blocks = (nSamples + 127) / 128;
    cnn_kernel<<<blocks, 128, SMEM_BYTES>>>(x, (float*)d_out, nSamples);
}